// round 8
// baseline (speedup 1.0000x reference)
#include <cuda_runtime.h>
#include <cuda_bf16.h>
#include <math.h>

#define BATCH  64
#define NPTS   128
#define FEAT   4
#define HID    100
#define NPAIRS 8128   // C(128,2)

// Folded weights: g_M[f][k] = sum_t W1[f][t]*W2[t][k] (f 0..7)
//                 g_d[k]    = b2[k] + sum_t b1[t]*W2[t][k]
__device__ __align__(16) float g_M[8 * HID];
__device__ __align__(16) float g_d[HID];

// 32x32 tile list over the 4x4 upper triangle (jt >= it): 10 tiles
__constant__ unsigned char TCI[10] = {0,0,0,0, 1,1,1, 2,2, 3};
__constant__ unsigned char TCJ[10] = {0,1,2,3, 1,2,3, 2,3, 3};

// ---- packed f32x2 helpers (sm_100+) --------------------------------------
__device__ __forceinline__ unsigned long long f2_add(unsigned long long a,
                                                     unsigned long long b) {
    unsigned long long d;
    asm("add.rn.f32x2 %0, %1, %2;" : "=l"(d) : "l"(a), "l"(b));
    return d;
}
__device__ __forceinline__ unsigned long long f2_fma(unsigned long long a,
                                                     unsigned long long b,
                                                     unsigned long long c) {
    unsigned long long d;
    asm("fma.rn.f32x2 %0, %1, %2, %3;" : "=l"(d) : "l"(a), "l"(b), "l"(c));
    return d;
}
__device__ __forceinline__ unsigned long long f2_pack(float lo, float hi) {
    unsigned long long d;
    asm("mov.b64 %0, {%1, %2};" : "=l"(d) : "f"(lo), "f"(hi));
    return d;
}
__device__ __forceinline__ void f2_unpack(unsigned long long v, float& lo, float& hi) {
    asm("mov.b64 {%0, %1}, %2;" : "=f"(lo), "=f"(hi) : "l"(v));
}
__device__ __forceinline__ unsigned long long f2_relu(unsigned long long t) {
    float lo, hi;
    f2_unpack(t, lo, hi);
    lo = fmaxf(lo, 0.f);
    hi = fmaxf(hi, 0.f);
    return f2_pack(lo, hi);
}

// ---------------------------------------------------------------------------
// Kernel 1: fold.  One warp per k (grid 100).  Lane-strided t, shfl-reduce.
// ---------------------------------------------------------------------------
__global__ __launch_bounds__(32)
void fold_kernel(const float* __restrict__ W1,   // [8,100]
                 const float* __restrict__ b1,   // [100]
                 const float* __restrict__ W2,   // [100,100]
                 const float* __restrict__ b2)   // [100]
{
    const int k   = blockIdx.x;
    const int lid = threadIdx.x;

    float acc[9] = {0.f,0.f,0.f,0.f,0.f,0.f,0.f,0.f,0.f};
    #pragma unroll
    for (int tb = 0; tb < 4; tb++) {
        int t = lid + tb * 32;
        if (t < HID) {
            float w2 = W2[t * HID + k];
            #pragma unroll
            for (int f = 0; f < 8; f++)
                acc[f] = fmaf(W1[f * HID + t], w2, acc[f]);
            acc[8] = fmaf(b1[t], w2, acc[8]);
        }
    }
    #pragma unroll
    for (int off = 16; off > 0; off >>= 1) {
        #pragma unroll
        for (int q = 0; q < 9; q++)
            acc[q] += __shfl_down_sync(0xffffffffu, acc[q], off);
    }
    if (lid == 0) {
        #pragma unroll
        for (int f = 0; f < 8; f++)
            g_M[f * HID + k] = acc[f];
        g_d[k] = acc[8] + b2[k];
    }
}

// ---------------------------------------------------------------------------
// Kernel 2: pair tiles with fused projection.  Launched with PDL so it
// overlaps fold: stages x/W3 first, then cudaGridDependencySynchronize()
// before consuming g_M/g_d.
// 32x32 tile, 256 threads = 4 k-groups x 64.  4i x 4j f32x2 slots per thread.
// Grid (10 tiles, 64 batches) = 640 CTAs, ~43 KB smem -> 5 CTAs/SM, 1 wave.
// ---------------------------------------------------------------------------
__global__ __launch_bounds__(256, 5)
void pair_kernel(const float* __restrict__ x,    // [64,128,4]
                 const float* __restrict__ W3,   // [100]
                 const float* __restrict__ b3,   // [1]
                 float* __restrict__ out)        // [64, 8128]
{
    __shared__ __align__(16) float aS[HID * 32];                // 12.8 KB
    __shared__ __align__(16) float cS[HID * 32];                // 12.8 KB
    __shared__ __align__(8)  float2 wS[HID];                    // 0.8 KB
    __shared__ __align__(16) unsigned long long redS[8 * 256];  // 16 KB

    // Prologue-only data aliased into redS (redS used strictly post-mainloop).
    float*  Ms = reinterpret_cast<float*>(redS);               // u64[0..400)
    float4* xi = reinterpret_cast<float4*>(redS + 512);        // 32 float4
    float4* xj = xi + 32;                                      // 32 float4
    float*  ds = reinterpret_cast<float*>(redS + 704);         // 100 floats

    const int tid  = threadIdx.x;
    const int tile = blockIdx.x;
    const int b    = blockIdx.y;
    const int i0   = TCI[tile] * 32;
    const int j0   = TCJ[tile] * 32;

    const int kg  = tid >> 6;        // k-group 0..3
    const int t64 = tid & 63;
    const int tj  = t64 & 7;         // 8 j-groups of 4
    const int ti  = t64 >> 3;        // 8 i-groups of 4

    // --- stage fold-independent data first (x tiles, W3) ---
    if (tid < 32)       xi[tid]      = reinterpret_cast<const float4*>(x)[b * NPTS + i0 + tid];
    else if (tid < 64)  xj[tid - 32] = reinterpret_cast<const float4*>(x)[b * NPTS + j0 + (tid - 32)];
    if (tid >= 128 && tid < 128 + HID) {
        int q = tid - 128;
        float w = __ldg(W3 + q);
        wS[q] = make_float2(w, w);
    }

    // --- wait for fold's g_M/g_d to be visible (PDL dependency) ---
    cudaGridDependencySynchronize();

    // --- stage M, d ---
    for (int q = tid; q < 200; q += 256)
        reinterpret_cast<float4*>(Ms)[q] = reinterpret_cast<const float4*>(g_M)[q];
    if (tid >= 64 && tid < 89)
        reinterpret_cast<float4*>(ds)[tid - 64] =
            reinterpret_cast<const float4*>(g_d)[tid - 64];
    __syncthreads();

    // --- projection, register-blocked: thread = (k-quad, point ii) ---
    // aS[k][ii] = d[k] + x_i . M[0:4][k];  cS[k][ii] = x_j . M[4:8][k]
    {
        const float4* Ms4 = reinterpret_cast<const float4*>(Ms);
        const float4* ds4 = reinterpret_cast<const float4*>(ds);
        for (int e = tid; e < 25 * 32; e += 256) {
            int kq = e >> 5;          // k-quad 0..24
            int ii = e & 31;
            float4 xv = xi[ii];
            float4 xw = xj[ii];
            float4 a  = ds4[kq];
            float4 c  = make_float4(0.f, 0.f, 0.f, 0.f);
            float4 m;
            m = Ms4[0 * 25 + kq];
            a.x = fmaf(xv.x, m.x, a.x); a.y = fmaf(xv.x, m.y, a.y);
            a.z = fmaf(xv.x, m.z, a.z); a.w = fmaf(xv.x, m.w, a.w);
            m = Ms4[1 * 25 + kq];
            a.x = fmaf(xv.y, m.x, a.x); a.y = fmaf(xv.y, m.y, a.y);
            a.z = fmaf(xv.y, m.z, a.z); a.w = fmaf(xv.y, m.w, a.w);
            m = Ms4[2 * 25 + kq];
            a.x = fmaf(xv.z, m.x, a.x); a.y = fmaf(xv.z, m.y, a.y);
            a.z = fmaf(xv.z, m.z, a.z); a.w = fmaf(xv.z, m.w, a.w);
            m = Ms4[3 * 25 + kq];
            a.x = fmaf(xv.w, m.x, a.x); a.y = fmaf(xv.w, m.y, a.y);
            a.z = fmaf(xv.w, m.z, a.z); a.w = fmaf(xv.w, m.w, a.w);
            m = Ms4[4 * 25 + kq];
            c.x = fmaf(xw.x, m.x, c.x); c.y = fmaf(xw.x, m.y, c.y);
            c.z = fmaf(xw.x, m.z, c.z); c.w = fmaf(xw.x, m.w, c.w);
            m = Ms4[5 * 25 + kq];
            c.x = fmaf(xw.y, m.x, c.x); c.y = fmaf(xw.y, m.y, c.y);
            c.z = fmaf(xw.y, m.z, c.z); c.w = fmaf(xw.y, m.w, c.w);
            m = Ms4[6 * 25 + kq];
            c.x = fmaf(xw.z, m.x, c.x); c.y = fmaf(xw.z, m.y, c.y);
            c.z = fmaf(xw.z, m.z, c.z); c.w = fmaf(xw.z, m.w, c.w);
            m = Ms4[7 * 25 + kq];
            c.x = fmaf(xw.w, m.x, c.x); c.y = fmaf(xw.w, m.y, c.y);
            c.z = fmaf(xw.w, m.z, c.z); c.w = fmaf(xw.w, m.w, c.w);
            int base = kq * 128 + ii;           // (4kq)*32 + ii
            aS[base      ] = a.x;  aS[base + 32] = a.y;
            aS[base +  64] = a.z;  aS[base + 96] = a.w;
            cS[base      ] = c.x;  cS[base + 32] = c.y;
            cS[base +  64] = c.z;  cS[base + 96] = c.w;
        }
    }
    __syncthreads();   // also fences the redS aliasing

    // --- main loop: 16 slots per thread, 25 k's per group, packed f32x2 ---
    unsigned long long acc[8] = {0ull,0ull,0ull,0ull,0ull,0ull,0ull,0ull};
    const float* aP = aS + ti * 4;
    const float* cP = cS + tj * 4;
    const unsigned long long* wP = reinterpret_cast<const unsigned long long*>(wS);
    const int kEnd = kg * 25 + 25;

    #pragma unroll 5
    for (int k = kg * 25; k < kEnd; k++) {
        float4 a4 = *reinterpret_cast<const float4*>(aP + k * 32);  // LDS.128
        float4 c4 = *reinterpret_cast<const float4*>(cP + k * 32);  // LDS.128
        unsigned long long w2 = wP[k];                               // LDS.64 bcast
        unsigned long long A01 = f2_pack(a4.x, a4.y);
        unsigned long long A23 = f2_pack(a4.z, a4.w);
        const float cj[4] = {c4.x, c4.y, c4.z, c4.w};
        #pragma unroll
        for (int jr = 0; jr < 4; jr++) {
            unsigned long long cd = f2_pack(cj[jr], cj[jr]);
            unsigned long long t0 = f2_relu(f2_add(A01, cd));
            unsigned long long t1 = f2_relu(f2_add(A23, cd));
            acc[jr * 2 + 0] = f2_fma(t0, w2, acc[jr * 2 + 0]);
            acc[jr * 2 + 1] = f2_fma(t1, w2, acc[jr * 2 + 1]);
        }
    }

    // --- all groups publish partials (conflict-free: t64 fastest) ---
    #pragma unroll
    for (int q = 0; q < 8; q++)
        redS[q * 256 + kg * 64 + t64] = acc[q];
    __syncthreads();

    // --- distributed finalize: group kg handles jr = kg, both i-halves ---
    {
        const int jr = kg;
        unsigned long long s0, s1;
        {
            const unsigned long long* r0 = redS + (jr * 2 + 0) * 256 + t64;
            const unsigned long long* r1 = redS + (jr * 2 + 1) * 256 + t64;
            s0 = f2_add(f2_add(r0[0], r0[64]), f2_add(r0[128], r0[192]));
            s1 = f2_add(f2_add(r1[0], r1[64]), f2_add(r1[128], r1[192]));
        }
        const float bias3 = __ldg(b3);
        float* outb = out + (size_t)b * NPAIRS;
        int j = j0 + tj * 4 + jr;
        float v[4];
        f2_unpack(s0, v[0], v[1]);
        f2_unpack(s1, v[2], v[3]);
        #pragma unroll
        for (int pi = 0; pi < 4; pi++) {
            int i = i0 + ti * 4 + pi;
            if (j > i) {
                int rb = i * (NPTS - 1) - ((i * (i - 1)) >> 1) - i - 1;
                float s = bias3 + v[pi];
                outb[rb + j] = __fdividef(1.f, 1.f + __expf(-s));
            }
        }
    }
}

// ---------------------------------------------------------------------------
extern "C" void kernel_launch(void* const* d_in, const int* in_sizes, int n_in,
                              void* d_out, int out_size)
{
    const float* x   = (const float*)d_in[0];
    // d_in[1] = in_hitnr (unused by the reference)
    const float* W1  = (const float*)d_in[2];
    const float* b1  = (const float*)d_in[3];
    const float* W2  = (const float*)d_in[4];
    const float* b2  = (const float*)d_in[5];
    const float* W3  = (const float*)d_in[6];
    const float* b3  = (const float*)d_in[7];
    float* out = (float*)d_out;

    fold_kernel<<<HID, 32>>>(W1, b1, W2, b2);

    // PDL launch: pair may begin while fold drains; pair's
    // cudaGridDependencySynchronize() orders the g_M/g_d reads.
    cudaLaunchConfig_t cfg = {};
    cfg.gridDim  = dim3(10, BATCH, 1);
    cfg.blockDim = dim3(256, 1, 1);
    cfg.dynamicSmemBytes = 0;
    cfg.stream = 0;
    cudaLaunchAttribute attrs[1];
    attrs[0].id = cudaLaunchAttributeProgrammaticStreamSerialization;
    attrs[0].val.programmaticStreamSerializationAllowed = 1;
    cfg.attrs = attrs;
    cfg.numAttrs = 1;
    cudaLaunchKernelEx(&cfg, pair_kernel, x, W3, b3, out);
}